// round 15
// baseline (speedup 1.0000x reference)
#include <cuda_runtime.h>
#include <cuda_bf16.h>

// Merged multi-hot embedding bag, sum pooling.
// B=32768, NT=26 tables, 214 packed index columns, DIM=128 fp32.
// Output: [B, 26*128] fp32.
//
// R14 design (best: 197.1us): persistent warps + mod-5 class rotation,
// 1184 blocks x 8 warps; u = g + k*9472 over BATCH*5 units, c = u mod 5.
// The interleave keeps DRAM-bound and L2-hit lookups mixed in time.
// Reuse-free big tables use __ldcs (evict-first) to protect L2 for the
// hot 5000-row tables.
//
// Streaming set this round: t0 (512MB), t1 (205MB), t2 (102MB),
//                           t3 (51MB), t5 (25.6MB), t6 (25.6MB)
// Cached: t4 (51MB but 6 hots -> ~2x reuse), all 5000-row tables.
//   c0: t20 (100)
//   c1: t21 (27) + t1 (2, STREAM)
//   c2: t19 (12) + t22 (10) + t14 (9)
//   c3: t11 (8) + t9 (7) + t4 (6) + t13 (6)
//   c4: t15 (5) + t0 (3, STREAM) + t10 (3) + t23 (3) + t3 (2, STREAM)
//       + 11 singles (t2, t5, t6 STREAM)

#define BATCH 32768
#define NT 26
#define TOTAL_COLS 214
#define DIM 128
#define NBLOCKS 1184
#define NWARPS (NBLOCKS * 8)          // 9472
#define NUNITS (BATCH * 5)            // 163840

// the 11 singleton tables: packed column per lane
// lanes: 0->t2(col5), 1->t5(col14), 2->t6(col15), 3->t7(col16), 4->t8(col17),
//        5->t12(col36), 6->t16(col57), 7->t17(col58), 8->t18(col59),
//        9->t24(col212), 10->t25(col213)
__constant__ int c_scol[11] = {5,14,15,16,17,36,57,58,59,212,213};

#define ROWF4(i) ((const float4*)(weights + (long long)(i) * DIM) + lane)

__device__ __forceinline__ float4 gather_sum(const int* __restrict__ idxp, int h,
                                             const float* __restrict__ weights, int lane)
{
    // h <= 32: one coalesced index load, broadcast via shfl
    int iv = 0;
    if (lane < h) iv = __ldg(idxp + lane);
    float4 acc = make_float4(0.f, 0.f, 0.f, 0.f);
    int k = 0;
    for (; k + 4 <= h; k += 4) {
        int i0 = __shfl_sync(0xffffffffu, iv, k);
        int i1 = __shfl_sync(0xffffffffu, iv, k + 1);
        int i2 = __shfl_sync(0xffffffffu, iv, k + 2);
        int i3 = __shfl_sync(0xffffffffu, iv, k + 3);
        float4 a0 = __ldg(ROWF4(i0));
        float4 a1 = __ldg(ROWF4(i1));
        float4 a2 = __ldg(ROWF4(i2));
        float4 a3 = __ldg(ROWF4(i3));
        acc.x += (a0.x + a1.x) + (a2.x + a3.x);
        acc.y += (a0.y + a1.y) + (a2.y + a3.y);
        acc.z += (a0.z + a1.z) + (a2.z + a3.z);
        acc.w += (a0.w + a1.w) + (a2.w + a3.w);
    }
    for (; k < h; k++) {
        int i0 = __shfl_sync(0xffffffffu, iv, k);
        float4 a0 = __ldg(ROWF4(i0));
        acc.x += a0.x; acc.y += a0.y; acc.z += a0.z; acc.w += a0.w;
    }
    return acc;
}

// streaming variant for reuse-free big tables (h <= 4 in practice)
__device__ __forceinline__ float4 gather_sum_cs(const int* __restrict__ idxp, int h,
                                                const float* __restrict__ weights, int lane)
{
    int iv = 0;
    if (lane < h) iv = __ldg(idxp + lane);
    float4 acc = make_float4(0.f, 0.f, 0.f, 0.f);
    for (int k = 0; k < h; k++) {
        int i0 = __shfl_sync(0xffffffffu, iv, k);
        float4 a0 = __ldcs(ROWF4(i0));
        acc.x += a0.x; acc.y += a0.y; acc.z += a0.z; acc.w += a0.w;
    }
    return acc;
}

__device__ __forceinline__ void bag_store(const int* __restrict__ rowidx, int s, int h,
                                          const float* __restrict__ weights, int lane,
                                          float* __restrict__ orow, int t)
{
    float4 acc = gather_sum(rowidx + s, h, weights, lane);
    __stcs((float4*)(orow + t * DIM) + lane, acc);
}

__device__ __forceinline__ void bag_store_cs(const int* __restrict__ rowidx, int s, int h,
                                             const float* __restrict__ weights, int lane,
                                             float* __restrict__ orow, int t)
{
    float4 acc = gather_sum_cs(rowidx + s, h, weights, lane);
    __stcs((float4*)(orow + t * DIM) + lane, acc);
}

__global__ __launch_bounds__(256, 8)
void merged_embed_bag_kernel(const int* __restrict__ indices,
                             const float* __restrict__ weights,
                             float* __restrict__ out)
{
    const int g    = blockIdx.x * 8 + (threadIdx.x >> 5);  // global warp id
    const int lane = threadIdx.x & 31;

    for (int u = g; u < NUNITS; u += NWARPS) {
        const int b = u / 5;
        const int c = u - b * 5;
        const int* rowidx = indices + (long long)b * TOTAL_COLS;
        float* orow = out + (long long)b * (NT * DIM);

        if (c == 0) {
            // ---- t20 whole: cols 72..171, 100 hots (3*32 + 4 index rounds) ----
            float4 acc = make_float4(0.f, 0.f, 0.f, 0.f);
            #pragma unroll
            for (int r = 0; r < 4; r++) {
                const int cnt = (r < 3) ? 32 : 4;
                int iv = 0;
                if (lane < cnt) iv = __ldg(rowidx + 72 + r * 32 + lane);
                for (int k = 0; k + 4 <= cnt; k += 4) {
                    int i0 = __shfl_sync(0xffffffffu, iv, k);
                    int i1 = __shfl_sync(0xffffffffu, iv, k + 1);
                    int i2 = __shfl_sync(0xffffffffu, iv, k + 2);
                    int i3 = __shfl_sync(0xffffffffu, iv, k + 3);
                    float4 a0 = __ldg(ROWF4(i0));
                    float4 a1 = __ldg(ROWF4(i1));
                    float4 a2 = __ldg(ROWF4(i2));
                    float4 a3 = __ldg(ROWF4(i3));
                    acc.x += (a0.x + a1.x) + (a2.x + a3.x);
                    acc.y += (a0.y + a1.y) + (a2.y + a3.y);
                    acc.z += (a0.z + a1.z) + (a2.z + a3.z);
                    acc.w += (a0.w + a1.w) + (a2.w + a3.w);
                }
            }
            __stcs((float4*)(orow + 20 * DIM) + lane, acc);
        } else if (c == 1) {
            bag_store(rowidx, 172, 27, weights, lane, orow, 21);
            bag_store_cs(rowidx, 3, 2, weights, lane, orow, 1);   // t1: 205MB, stream
        } else if (c == 2) {
            bag_store(rowidx,  60, 12, weights, lane, orow, 19);
            bag_store(rowidx, 199, 10, weights, lane, orow, 22);
            bag_store(rowidx,  43,  9, weights, lane, orow, 14);
        } else if (c == 3) {
            bag_store(rowidx, 28, 8, weights, lane, orow, 11);
            bag_store(rowidx, 18, 7, weights, lane, orow,  9);
            bag_store(rowidx,  8, 6, weights, lane, orow,  4);    // t4: ~2x reuse, cached
            bag_store(rowidx, 37, 6, weights, lane, orow, 13);
        } else {
            bag_store(rowidx,  52, 5, weights, lane, orow, 15);
            bag_store_cs(rowidx, 0, 3, weights, lane, orow, 0);   // t0: 512MB, stream
            bag_store(rowidx,  25, 3, weights, lane, orow, 10);
            bag_store(rowidx, 209, 3, weights, lane, orow, 23);
            bag_store_cs(rowidx, 6, 2, weights, lane, orow, 3);   // t3: 51MB, stream

            // 11 singles: coalesced idx load + shfl, independent copies
            int iv = 0;
            if (lane < 11) iv = __ldg(rowidx + c_scol[lane]);
            int i0 = __shfl_sync(0xffffffffu, iv, 0);
            int i1 = __shfl_sync(0xffffffffu, iv, 1);
            int i2 = __shfl_sync(0xffffffffu, iv, 2);
            int i3 = __shfl_sync(0xffffffffu, iv, 3);
            float4 a0 = __ldcs(ROWF4(i0));    // t2: 102MB, stream
            float4 a1 = __ldcs(ROWF4(i1));    // t5: 25.6MB, stream
            float4 a2 = __ldcs(ROWF4(i2));    // t6: 25.6MB, stream
            float4 a3 = __ldg(ROWF4(i3));     // t7: 2.56MB hot
            __stcs((float4*)(orow +  2 * DIM) + lane, a0);
            __stcs((float4*)(orow +  5 * DIM) + lane, a1);
            __stcs((float4*)(orow +  6 * DIM) + lane, a2);
            __stcs((float4*)(orow +  7 * DIM) + lane, a3);
            int i4 = __shfl_sync(0xffffffffu, iv, 4);
            int i5 = __shfl_sync(0xffffffffu, iv, 5);
            int i6 = __shfl_sync(0xffffffffu, iv, 6);
            int i7 = __shfl_sync(0xffffffffu, iv, 7);
            float4 a4 = __ldg(ROWF4(i4));
            float4 a5 = __ldg(ROWF4(i5));
            float4 a6 = __ldg(ROWF4(i6));
            float4 a7 = __ldg(ROWF4(i7));
            __stcs((float4*)(orow +  8 * DIM) + lane, a4);
            __stcs((float4*)(orow + 12 * DIM) + lane, a5);
            __stcs((float4*)(orow + 16 * DIM) + lane, a6);
            __stcs((float4*)(orow + 17 * DIM) + lane, a7);
            int i8 = __shfl_sync(0xffffffffu, iv, 8);
            int i9 = __shfl_sync(0xffffffffu, iv, 9);
            int i10 = __shfl_sync(0xffffffffu, iv, 10);
            float4 a8 = __ldg(ROWF4(i8));
            float4 a9 = __ldg(ROWF4(i9));
            float4 a10 = __ldg(ROWF4(i10));
            __stcs((float4*)(orow + 18 * DIM) + lane, a8);
            __stcs((float4*)(orow + 24 * DIM) + lane, a9);
            __stcs((float4*)(orow + 25 * DIM) + lane, a10);
        }
    }
}

extern "C" void kernel_launch(void* const* d_in, const int* in_sizes, int n_in,
                              void* d_out, int out_size)
{
    const int* indices = nullptr;
    const float* weights = nullptr;
    const long long idx_elems = (long long)BATCH * TOTAL_COLS;
    for (int i = 0; i < n_in; i++) {
        if ((long long)in_sizes[i] == idx_elems) indices = (const int*)d_in[i];
        else weights = (const float*)d_in[i];
    }
    float* out = (float*)d_out;

    merged_embed_bag_kernel<<<NBLOCKS, 256>>>(indices, weights, out);
}

// round 16
// speedup vs baseline: 1.0091x; 1.0091x over previous
#include <cuda_runtime.h>
#include <cuda_bf16.h>

// Merged multi-hot embedding bag, sum pooling.
// B=32768, NT=26 tables, 214 packed index columns, DIM=128 fp32.
// Output: [B, 26*128] fp32.
//
// R14 design (best: 197.1us): persistent warps + mod-5 class rotation,
// 1184 blocks x 8 warps; u = g + k*9472 over BATCH*5 units, c = u mod 5.
// The interleave keeps DRAM-bound and L2-hit lookups mixed in time.
//
// Streaming (__ldcs, evict-first) set: weight rows of the reuse-free giant
// tables t0 (512MB), t1 (205MB), t2 (102MB) ONLY (R15 showed extending to
// t3/t5/t6 regresses). NEW: index vectors are also streamed -- indices are
// read exactly once per kernel, so caching them is pure L2 pollution.
//   c0: t20 (100)
//   c1: t21 (27) + t1 (2, STREAM)
//   c2: t19 (12) + t22 (10) + t14 (9)
//   c3: t11 (8) + t9 (7) + t4 (6) + t13 (6)
//   c4: t15 (5) + t0 (3, STREAM) + t10 (3) + t23 (3) + t3 (2)
//       + 11 singles (t2 single STREAM)

#define BATCH 32768
#define NT 26
#define TOTAL_COLS 214
#define DIM 128
#define NBLOCKS 1184
#define NWARPS (NBLOCKS * 8)          // 9472
#define NUNITS (BATCH * 5)            // 163840

// the 11 singleton tables: packed column per lane
__constant__ int c_scol[11] = {5,14,15,16,17,36,57,58,59,212,213};

#define ROWF4(i) ((const float4*)(weights + (long long)(i) * DIM) + lane)

__device__ __forceinline__ float4 gather_sum(const int* __restrict__ idxp, int h,
                                             const float* __restrict__ weights, int lane)
{
    // h <= 32: one coalesced index load (streamed: single-use data), shfl broadcast
    int iv = 0;
    if (lane < h) iv = __ldcs(idxp + lane);
    float4 acc = make_float4(0.f, 0.f, 0.f, 0.f);
    int k = 0;
    for (; k + 4 <= h; k += 4) {
        int i0 = __shfl_sync(0xffffffffu, iv, k);
        int i1 = __shfl_sync(0xffffffffu, iv, k + 1);
        int i2 = __shfl_sync(0xffffffffu, iv, k + 2);
        int i3 = __shfl_sync(0xffffffffu, iv, k + 3);
        float4 a0 = __ldg(ROWF4(i0));
        float4 a1 = __ldg(ROWF4(i1));
        float4 a2 = __ldg(ROWF4(i2));
        float4 a3 = __ldg(ROWF4(i3));
        acc.x += (a0.x + a1.x) + (a2.x + a3.x);
        acc.y += (a0.y + a1.y) + (a2.y + a3.y);
        acc.z += (a0.z + a1.z) + (a2.z + a3.z);
        acc.w += (a0.w + a1.w) + (a2.w + a3.w);
    }
    for (; k < h; k++) {
        int i0 = __shfl_sync(0xffffffffu, iv, k);
        float4 a0 = __ldg(ROWF4(i0));
        acc.x += a0.x; acc.y += a0.y; acc.z += a0.z; acc.w += a0.w;
    }
    return acc;
}

// streaming variant for reuse-free big tables (h <= 4 in practice)
__device__ __forceinline__ float4 gather_sum_cs(const int* __restrict__ idxp, int h,
                                                const float* __restrict__ weights, int lane)
{
    int iv = 0;
    if (lane < h) iv = __ldcs(idxp + lane);
    float4 acc = make_float4(0.f, 0.f, 0.f, 0.f);
    for (int k = 0; k < h; k++) {
        int i0 = __shfl_sync(0xffffffffu, iv, k);
        float4 a0 = __ldcs(ROWF4(i0));
        acc.x += a0.x; acc.y += a0.y; acc.z += a0.z; acc.w += a0.w;
    }
    return acc;
}

__device__ __forceinline__ void bag_store(const int* __restrict__ rowidx, int s, int h,
                                          const float* __restrict__ weights, int lane,
                                          float* __restrict__ orow, int t)
{
    float4 acc = gather_sum(rowidx + s, h, weights, lane);
    __stcs((float4*)(orow + t * DIM) + lane, acc);
}

__device__ __forceinline__ void bag_store_cs(const int* __restrict__ rowidx, int s, int h,
                                             const float* __restrict__ weights, int lane,
                                             float* __restrict__ orow, int t)
{
    float4 acc = gather_sum_cs(rowidx + s, h, weights, lane);
    __stcs((float4*)(orow + t * DIM) + lane, acc);
}

__global__ __launch_bounds__(256, 8)
void merged_embed_bag_kernel(const int* __restrict__ indices,
                             const float* __restrict__ weights,
                             float* __restrict__ out)
{
    const int g    = blockIdx.x * 8 + (threadIdx.x >> 5);  // global warp id
    const int lane = threadIdx.x & 31;

    for (int u = g; u < NUNITS; u += NWARPS) {
        const int b = u / 5;
        const int c = u - b * 5;
        const int* rowidx = indices + (long long)b * TOTAL_COLS;
        float* orow = out + (long long)b * (NT * DIM);

        if (c == 0) {
            // ---- t20 whole: cols 72..171, 100 hots (3*32 + 4 index rounds) ----
            float4 acc = make_float4(0.f, 0.f, 0.f, 0.f);
            #pragma unroll
            for (int r = 0; r < 4; r++) {
                const int cnt = (r < 3) ? 32 : 4;
                int iv = 0;
                if (lane < cnt) iv = __ldcs(rowidx + 72 + r * 32 + lane);
                for (int k = 0; k + 4 <= cnt; k += 4) {
                    int i0 = __shfl_sync(0xffffffffu, iv, k);
                    int i1 = __shfl_sync(0xffffffffu, iv, k + 1);
                    int i2 = __shfl_sync(0xffffffffu, iv, k + 2);
                    int i3 = __shfl_sync(0xffffffffu, iv, k + 3);
                    float4 a0 = __ldg(ROWF4(i0));
                    float4 a1 = __ldg(ROWF4(i1));
                    float4 a2 = __ldg(ROWF4(i2));
                    float4 a3 = __ldg(ROWF4(i3));
                    acc.x += (a0.x + a1.x) + (a2.x + a3.x);
                    acc.y += (a0.y + a1.y) + (a2.y + a3.y);
                    acc.z += (a0.z + a1.z) + (a2.z + a3.z);
                    acc.w += (a0.w + a1.w) + (a2.w + a3.w);
                }
            }
            __stcs((float4*)(orow + 20 * DIM) + lane, acc);
        } else if (c == 1) {
            bag_store(rowidx, 172, 27, weights, lane, orow, 21);
            bag_store_cs(rowidx, 3, 2, weights, lane, orow, 1);   // t1: 205MB, stream
        } else if (c == 2) {
            bag_store(rowidx,  60, 12, weights, lane, orow, 19);
            bag_store(rowidx, 199, 10, weights, lane, orow, 22);
            bag_store(rowidx,  43,  9, weights, lane, orow, 14);
        } else if (c == 3) {
            bag_store(rowidx, 28, 8, weights, lane, orow, 11);
            bag_store(rowidx, 18, 7, weights, lane, orow,  9);
            bag_store(rowidx,  8, 6, weights, lane, orow,  4);
            bag_store(rowidx, 37, 6, weights, lane, orow, 13);
        } else {
            bag_store(rowidx,  52, 5, weights, lane, orow, 15);
            bag_store_cs(rowidx, 0, 3, weights, lane, orow, 0);   // t0: 512MB, stream
            bag_store(rowidx,  25, 3, weights, lane, orow, 10);
            bag_store(rowidx, 209, 3, weights, lane, orow, 23);
            bag_store(rowidx,   6, 2, weights, lane, orow,  3);

            // 11 singles: coalesced idx load + shfl, independent copies
            int iv = 0;
            if (lane < 11) iv = __ldcs(rowidx + c_scol[lane]);
            int i0 = __shfl_sync(0xffffffffu, iv, 0);
            int i1 = __shfl_sync(0xffffffffu, iv, 1);
            int i2 = __shfl_sync(0xffffffffu, iv, 2);
            int i3 = __shfl_sync(0xffffffffu, iv, 3);
            float4 a0 = __ldcs(ROWF4(i0));    // t2: 102MB, stream
            float4 a1 = __ldg(ROWF4(i1));
            float4 a2 = __ldg(ROWF4(i2));
            float4 a3 = __ldg(ROWF4(i3));
            __stcs((float4*)(orow +  2 * DIM) + lane, a0);
            __stcs((float4*)(orow +  5 * DIM) + lane, a1);
            __stcs((float4*)(orow +  6 * DIM) + lane, a2);
            __stcs((float4*)(orow +  7 * DIM) + lane, a3);
            int i4 = __shfl_sync(0xffffffffu, iv, 4);
            int i5 = __shfl_sync(0xffffffffu, iv, 5);
            int i6 = __shfl_sync(0xffffffffu, iv, 6);
            int i7 = __shfl_sync(0xffffffffu, iv, 7);
            float4 a4 = __ldg(ROWF4(i4));
            float4 a5 = __ldg(ROWF4(i5));
            float4 a6 = __ldg(ROWF4(i6));
            float4 a7 = __ldg(ROWF4(i7));
            __stcs((float4*)(orow +  8 * DIM) + lane, a4);
            __stcs((float4*)(orow + 12 * DIM) + lane, a5);
            __stcs((float4*)(orow + 16 * DIM) + lane, a6);
            __stcs((float4*)(orow + 17 * DIM) + lane, a7);
            int i8 = __shfl_sync(0xffffffffu, iv, 8);
            int i9 = __shfl_sync(0xffffffffu, iv, 9);
            int i10 = __shfl_sync(0xffffffffu, iv, 10);
            float4 a8 = __ldg(ROWF4(i8));
            float4 a9 = __ldg(ROWF4(i9));
            float4 a10 = __ldg(ROWF4(i10));
            __stcs((float4*)(orow + 18 * DIM) + lane, a8);
            __stcs((float4*)(orow + 24 * DIM) + lane, a9);
            __stcs((float4*)(orow + 25 * DIM) + lane, a10);
        }
    }
}

extern "C" void kernel_launch(void* const* d_in, const int* in_sizes, int n_in,
                              void* d_out, int out_size)
{
    const int* indices = nullptr;
    const float* weights = nullptr;
    const long long idx_elems = (long long)BATCH * TOTAL_COLS;
    for (int i = 0; i < n_in; i++) {
        if ((long long)in_sizes[i] == idx_elems) indices = (const int*)d_in[i];
        else weights = (const float*)d_in[i];
    }
    float* out = (float*)d_out;

    merged_embed_bag_kernel<<<NBLOCKS, 256>>>(indices, weights, out);
}

// round 17
// speedup vs baseline: 1.0233x; 1.0140x over previous
#include <cuda_runtime.h>
#include <cuda_bf16.h>

// Merged multi-hot embedding bag, sum pooling.
// B=32768, NT=26 tables, 214 packed index columns, DIM=128 fp32.
// Output: [B, 26*128] fp32.
//
// CONVERGED DESIGN (R14, best measured 197.1us):
// - persistent warps: 1184 blocks x 8 warps = 9472 resident (8/SM, 32 regs)
// - mod-5 class rotation: u = g + k*9472 over BATCH*5 units, c = u mod 5;
//   interleaves DRAM-bound and L2-hit lookups in time, equalizes per-warp
//   work without barriers or shared memory
// - warp-cooperative gather: coalesced index load + shfl broadcast,
//   4 independent LDG.128 row loads in flight (MLP 4)
// - L2 policy: __ldcs (evict-first) ONLY for the reuse-free giant tables
//   t0 (512MB), t1 (205MB), t2 (102MB); everything else cached;
//   output stores are __stcs (streaming, protects L2 for weights)
//   c0: t20 (100)
//   c1: t21 (27) + t1 (2, STREAM)
//   c2: t19 (12) + t22 (10) + t14 (9)
//   c3: t11 (8) + t9 (7) + t4 (6) + t13 (6)
//   c4: t15 (5) + t0 (3, STREAM) + t10 (3) + t23 (3) + t3 (2)
//       + 11 singles (t2 single STREAM)

#define BATCH 32768
#define NT 26
#define TOTAL_COLS 214
#define DIM 128
#define NBLOCKS 1184
#define NWARPS (NBLOCKS * 8)          // 9472
#define NUNITS (BATCH * 5)            // 163840

// the 11 singleton tables: packed column per lane
__constant__ int c_scol[11] = {5,14,15,16,17,36,57,58,59,212,213};

#define ROWF4(i) ((const float4*)(weights + (long long)(i) * DIM) + lane)

__device__ __forceinline__ float4 gather_sum(const int* __restrict__ idxp, int h,
                                             const float* __restrict__ weights, int lane)
{
    // h <= 32: one coalesced index load, broadcast via shfl
    int iv = 0;
    if (lane < h) iv = __ldg(idxp + lane);
    float4 acc = make_float4(0.f, 0.f, 0.f, 0.f);
    int k = 0;
    for (; k + 4 <= h; k += 4) {
        int i0 = __shfl_sync(0xffffffffu, iv, k);
        int i1 = __shfl_sync(0xffffffffu, iv, k + 1);
        int i2 = __shfl_sync(0xffffffffu, iv, k + 2);
        int i3 = __shfl_sync(0xffffffffu, iv, k + 3);
        float4 a0 = __ldg(ROWF4(i0));
        float4 a1 = __ldg(ROWF4(i1));
        float4 a2 = __ldg(ROWF4(i2));
        float4 a3 = __ldg(ROWF4(i3));
        acc.x += (a0.x + a1.x) + (a2.x + a3.x);
        acc.y += (a0.y + a1.y) + (a2.y + a3.y);
        acc.z += (a0.z + a1.z) + (a2.z + a3.z);
        acc.w += (a0.w + a1.w) + (a2.w + a3.w);
    }
    for (; k < h; k++) {
        int i0 = __shfl_sync(0xffffffffu, iv, k);
        float4 a0 = __ldg(ROWF4(i0));
        acc.x += a0.x; acc.y += a0.y; acc.z += a0.z; acc.w += a0.w;
    }
    return acc;
}

// streaming variant for reuse-free big tables (h <= 4 in practice)
__device__ __forceinline__ float4 gather_sum_cs(const int* __restrict__ idxp, int h,
                                                const float* __restrict__ weights, int lane)
{
    int iv = 0;
    if (lane < h) iv = __ldg(idxp + lane);
    float4 acc = make_float4(0.f, 0.f, 0.f, 0.f);
    for (int k = 0; k < h; k++) {
        int i0 = __shfl_sync(0xffffffffu, iv, k);
        float4 a0 = __ldcs(ROWF4(i0));
        acc.x += a0.x; acc.y += a0.y; acc.z += a0.z; acc.w += a0.w;
    }
    return acc;
}

__device__ __forceinline__ void bag_store(const int* __restrict__ rowidx, int s, int h,
                                          const float* __restrict__ weights, int lane,
                                          float* __restrict__ orow, int t)
{
    float4 acc = gather_sum(rowidx + s, h, weights, lane);
    __stcs((float4*)(orow + t * DIM) + lane, acc);
}

__device__ __forceinline__ void bag_store_cs(const int* __restrict__ rowidx, int s, int h,
                                             const float* __restrict__ weights, int lane,
                                             float* __restrict__ orow, int t)
{
    float4 acc = gather_sum_cs(rowidx + s, h, weights, lane);
    __stcs((float4*)(orow + t * DIM) + lane, acc);
}

__global__ __launch_bounds__(256, 8)
void merged_embed_bag_kernel(const int* __restrict__ indices,
                             const float* __restrict__ weights,
                             float* __restrict__ out)
{
    const int g    = blockIdx.x * 8 + (threadIdx.x >> 5);  // global warp id
    const int lane = threadIdx.x & 31;

    for (int u = g; u < NUNITS; u += NWARPS) {
        const int b = u / 5;
        const int c = u - b * 5;
        const int* rowidx = indices + (long long)b * TOTAL_COLS;
        float* orow = out + (long long)b * (NT * DIM);

        if (c == 0) {
            // ---- t20 whole: cols 72..171, 100 hots (3*32 + 4 index rounds) ----
            float4 acc = make_float4(0.f, 0.f, 0.f, 0.f);
            #pragma unroll
            for (int r = 0; r < 4; r++) {
                const int cnt = (r < 3) ? 32 : 4;
                int iv = 0;
                if (lane < cnt) iv = __ldg(rowidx + 72 + r * 32 + lane);
                for (int k = 0; k + 4 <= cnt; k += 4) {
                    int i0 = __shfl_sync(0xffffffffu, iv, k);
                    int i1 = __shfl_sync(0xffffffffu, iv, k + 1);
                    int i2 = __shfl_sync(0xffffffffu, iv, k + 2);
                    int i3 = __shfl_sync(0xffffffffu, iv, k + 3);
                    float4 a0 = __ldg(ROWF4(i0));
                    float4 a1 = __ldg(ROWF4(i1));
                    float4 a2 = __ldg(ROWF4(i2));
                    float4 a3 = __ldg(ROWF4(i3));
                    acc.x += (a0.x + a1.x) + (a2.x + a3.x);
                    acc.y += (a0.y + a1.y) + (a2.y + a3.y);
                    acc.z += (a0.z + a1.z) + (a2.z + a3.z);
                    acc.w += (a0.w + a1.w) + (a2.w + a3.w);
                }
            }
            __stcs((float4*)(orow + 20 * DIM) + lane, acc);
        } else if (c == 1) {
            bag_store(rowidx, 172, 27, weights, lane, orow, 21);
            bag_store_cs(rowidx, 3, 2, weights, lane, orow, 1);   // t1: 205MB, stream
        } else if (c == 2) {
            bag_store(rowidx,  60, 12, weights, lane, orow, 19);
            bag_store(rowidx, 199, 10, weights, lane, orow, 22);
            bag_store(rowidx,  43,  9, weights, lane, orow, 14);
        } else if (c == 3) {
            bag_store(rowidx, 28, 8, weights, lane, orow, 11);
            bag_store(rowidx, 18, 7, weights, lane, orow,  9);
            bag_store(rowidx,  8, 6, weights, lane, orow,  4);
            bag_store(rowidx, 37, 6, weights, lane, orow, 13);
        } else {
            bag_store(rowidx,  52, 5, weights, lane, orow, 15);
            bag_store_cs(rowidx, 0, 3, weights, lane, orow, 0);   // t0: 512MB, stream
            bag_store(rowidx,  25, 3, weights, lane, orow, 10);
            bag_store(rowidx, 209, 3, weights, lane, orow, 23);
            bag_store(rowidx,   6, 2, weights, lane, orow,  3);

            // 11 singles: coalesced idx load + shfl, independent copies
            int iv = 0;
            if (lane < 11) iv = __ldg(rowidx + c_scol[lane]);
            int i0 = __shfl_sync(0xffffffffu, iv, 0);
            int i1 = __shfl_sync(0xffffffffu, iv, 1);
            int i2 = __shfl_sync(0xffffffffu, iv, 2);
            int i3 = __shfl_sync(0xffffffffu, iv, 3);
            float4 a0 = __ldcs(ROWF4(i0));    // t2: 102MB, stream
            float4 a1 = __ldg(ROWF4(i1));
            float4 a2 = __ldg(ROWF4(i2));
            float4 a3 = __ldg(ROWF4(i3));
            __stcs((float4*)(orow +  2 * DIM) + lane, a0);
            __stcs((float4*)(orow +  5 * DIM) + lane, a1);
            __stcs((float4*)(orow +  6 * DIM) + lane, a2);
            __stcs((float4*)(orow +  7 * DIM) + lane, a3);
            int i4 = __shfl_sync(0xffffffffu, iv, 4);
            int i5 = __shfl_sync(0xffffffffu, iv, 5);
            int i6 = __shfl_sync(0xffffffffu, iv, 6);
            int i7 = __shfl_sync(0xffffffffu, iv, 7);
            float4 a4 = __ldg(ROWF4(i4));
            float4 a5 = __ldg(ROWF4(i5));
            float4 a6 = __ldg(ROWF4(i6));
            float4 a7 = __ldg(ROWF4(i7));
            __stcs((float4*)(orow +  8 * DIM) + lane, a4);
            __stcs((float4*)(orow + 12 * DIM) + lane, a5);
            __stcs((float4*)(orow + 16 * DIM) + lane, a6);
            __stcs((float4*)(orow + 17 * DIM) + lane, a7);
            int i8 = __shfl_sync(0xffffffffu, iv, 8);
            int i9 = __shfl_sync(0xffffffffu, iv, 9);
            int i10 = __shfl_sync(0xffffffffu, iv, 10);
            float4 a8 = __ldg(ROWF4(i8));
            float4 a9 = __ldg(ROWF4(i9));
            float4 a10 = __ldg(ROWF4(i10));
            __stcs((float4*)(orow + 18 * DIM) + lane, a8);
            __stcs((float4*)(orow + 24 * DIM) + lane, a9);
            __stcs((float4*)(orow + 25 * DIM) + lane, a10);
        }
    }
}

extern "C" void kernel_launch(void* const* d_in, const int* in_sizes, int n_in,
                              void* d_out, int out_size)
{
    const int* indices = nullptr;
    const float* weights = nullptr;
    const long long idx_elems = (long long)BATCH * TOTAL_COLS;
    for (int i = 0; i < n_in; i++) {
        if ((long long)in_sizes[i] == idx_elems) indices = (const int*)d_in[i];
        else weights = (const float*)d_in[i];
    }
    float* out = (float*)d_out;

    merged_embed_bag_kernel<<<NBLOCKS, 256>>>(indices, weights, out);
}